// round 14
// baseline (speedup 1.0000x reference)
#include <cuda_runtime.h>
#include <cuda_fp16.h>

#define N_STU   10000
#define N_ITEM  50000
#define N_CONC  2048
#define EDGES   250000
#define KC      4
#define EMB     64
#define CNUM    128

#define PB_STU   313     // ceil(10000/32)
#define PB_ITEM  1563    // ceil(50000/32)
#define PB_CONC  64      // 2048/32
#define PB_TOT   (PB_STU + PB_ITEM + 2 * PB_CONC)

// fp16 tables, values pre-multiplied by 0.5 (for the tanh half-angle form).
__device__ __half g_stu_proj [N_STU  * CNUM];      //  2.56 MB
__device__ __half g_item_proj[N_ITEM * CNUM];      // 12.8  MB
// Fused concept table: row q = [ stu side (128) | item side (128) ], 512 B/row.
__device__ __half g_conc_fused[N_CONC * 2 * CNUM]; //  1.0  MB
// Sign-folded, 0.5-scaled w as half2, one uint4 per lane (lanes 16-31 negated).
__device__ uint4  g_w_tbl[32];

namespace {

__device__ __forceinline__ __half2 dg_tanh2(__half2 x)
{
    unsigned r, xi = *reinterpret_cast<unsigned*>(&x);
    asm("tanh.approx.f16x2 %0, %1;" : "=r"(r) : "r"(xi));
    return *reinterpret_cast<__half2*>(&r);
}

__device__ __forceinline__ float dg_tanhf(float x)
{
    float r;
    asm("tanh.approx.f32 %0, %1;" : "=f"(r) : "f"(x));
    return r;
}

// sigmoid(x) = 0.5 + 0.5*tanh(x/2): ONE MUFU op, no divide.
__device__ __forceinline__ float dg_sigmoid(float x)
{
    return fmaf(0.5f, dg_tanhf(0.5f * x), 0.5f);
}

__device__ __forceinline__ void dg_mma(float d[4],
                                       unsigned a0, unsigned a1, unsigned a2, unsigned a3,
                                       unsigned b0, unsigned b1)
{
    asm volatile(
        "mma.sync.aligned.m16n8k8.row.col.f32.tf32.tf32.f32 "
        "{%0,%1,%2,%3}, {%4,%5,%6,%7}, {%8,%9}, {%0,%1,%2,%3};"
        : "+f"(d[0]), "+f"(d[1]), "+f"(d[2]), "+f"(d[3])
        : "r"(a0), "r"(a1), "r"(a2), "r"(a3), "r"(b0), "r"(b1));
}

// Tensor-core tile: out_half[row*stride + coloff + c] = 0.5 * sum_e fusion[row,e] * W[c, col_off+e]
// Block: 32 rows x 128 cols, 256 threads = 8 warps (2 m-tiles x 4 n-strips of 32).
// Raw f32 bits are fed to mma.tf32 (HW reads tf32 bits = implicit RZ truncate);
// no explicit cvt needed. Epilogue repacked through smem for STG.128.
__device__ __forceinline__
void proj_tile(const float* __restrict__ fusion,
               const float* __restrict__ W,
               int col_off, int nrows, int row0,
               __half* __restrict__ out, int out_stride, int out_coloff)
{
    // stride 68: 68 mod 32 == 4 -> fragment banks = 4*(lane/4) + lane%4, all distinct
    __shared__ unsigned Fsm[32][68];     // F[r][e], f32 bits (reused as store buffer)
    __shared__ unsigned Wsm[CNUM][68];   // W[c][e], f32 bits

    const int tid = threadIdx.x;

    // W: 128 rows x 16 float4
    for (int idx = tid; idx < CNUM * (EMB / 4); idx += 256) {
        int c = idx >> 4;
        int f = idx & 15;
        float4 v = __ldg(reinterpret_cast<const float4*>(W + c * (2 * EMB) + col_off) + f);
        Wsm[c][f * 4 + 0] = __float_as_uint(v.x);
        Wsm[c][f * 4 + 1] = __float_as_uint(v.y);
        Wsm[c][f * 4 + 2] = __float_as_uint(v.z);
        Wsm[c][f * 4 + 3] = __float_as_uint(v.w);
    }
    // F: 32 rows x 16 float4
    for (int idx = tid; idx < 32 * (EMB / 4); idx += 256) {
        int r = idx >> 4;
        int f = idx & 15;
        int row = row0 + r;
        float4 v = make_float4(0.f, 0.f, 0.f, 0.f);
        if (row < nrows)
            v = __ldg(reinterpret_cast<const float4*>(fusion + row * EMB) + f);
        Fsm[r][f * 4 + 0] = __float_as_uint(v.x);
        Fsm[r][f * 4 + 1] = __float_as_uint(v.y);
        Fsm[r][f * 4 + 2] = __float_as_uint(v.z);
        Fsm[r][f * 4 + 3] = __float_as_uint(v.w);
    }
    __syncthreads();

    const int warp = tid >> 5;
    const int lane = tid & 31;
    const int qr   = lane >> 2;   // 0..7
    const int qc   = lane & 3;    // 0..3

    const int r0 = (warp & 1) * 16;        // m-tile
    const int n0 = (warp >> 1) * 32;       // n-strip

    float d[4][4];
    #pragma unroll
    for (int nt = 0; nt < 4; nt++)
        #pragma unroll
        for (int j = 0; j < 4; j++) d[nt][j] = 0.0f;

    #pragma unroll
    for (int ks = 0; ks < 8; ks++) {
        const int k0 = ks * 8;
        unsigned a0 = Fsm[r0 + qr    ][k0 + qc    ];
        unsigned a1 = Fsm[r0 + qr + 8][k0 + qc    ];
        unsigned a2 = Fsm[r0 + qr    ][k0 + qc + 4];
        unsigned a3 = Fsm[r0 + qr + 8][k0 + qc + 4];
        #pragma unroll
        for (int nt = 0; nt < 4; nt++) {
            const int n = n0 + nt * 8;
            unsigned b0 = Wsm[n + qr][k0 + qc    ];
            unsigned b1 = Wsm[n + qr][k0 + qc + 4];
            dg_mma(d[nt], a0, a1, a2, a3, b0, b1);
        }
    }

    // Repack through smem for coalesced STG.128.
    // Buffer: 32 rows x 128 halfs, row stride 136 halfs (272 B = 68 words).
    // STS bank = (68*r + col/2) % 32 = (4*qr + qc): conflict-free.
    // Total 32*136*2 = 8704 B = sizeof(Fsm): exact reuse.
    __syncthreads();   // done reading Fsm
    __half* sbuf = reinterpret_cast<__half*>(&Fsm[0][0]);
    #pragma unroll
    for (int nt = 0; nt < 4; nt++) {
        const int col = n0 + nt * 8 + qc * 2;
        *reinterpret_cast<__half2*>(sbuf + (r0 + qr) * 136 + col) =
            __floats2half2_rn(d[nt][0] * 0.5f, d[nt][1] * 0.5f);
        *reinterpret_cast<__half2*>(sbuf + (r0 + qr + 8) * 136 + col) =
            __floats2half2_rn(d[nt][2] * 0.5f, d[nt][3] * 0.5f);
    }
    __syncthreads();

    // 32 rows x 16 uint4 = 512 stores; thread t -> row t>>3, chunks (t&7), (t&7)+8.
    {
        const int r = tid >> 3;
        const int j = tid & 7;
        const int row = row0 + r;
        if (row < nrows) {
            const uint4* src = reinterpret_cast<const uint4*>(sbuf + r * 136);
            uint4* dst = reinterpret_cast<uint4*>(out + row * out_stride + out_coloff);
            dst[j]     = src[j];
            dst[j + 8] = src[j + 8];
        }
    }
}

} // anonymous namespace

// All four projections + the w-table build in ONE launch.
// Block PB_TOT (the extra last block) builds the sign-folded w table.
__global__ __launch_bounds__(256)
void proj_all(const float* __restrict__ stu_fusion,
              const float* __restrict__ item_fusion,
              const float* __restrict__ conc_fusion,
              const float* __restrict__ W_stu,
              const float* __restrict__ W_item,
              const float* __restrict__ w_pred,
              __half* p_sp, __half* p_ip, __half* p_cf)
{
    int b = blockIdx.x;
    if (b < PB_STU) {
        proj_tile(stu_fusion, W_stu, 0, N_STU, b * 32, p_sp, CNUM, 0);
    } else if (b < PB_STU + PB_ITEM) {
        proj_tile(item_fusion, W_item, 0, N_ITEM, (b - PB_STU) * 32, p_ip, CNUM, 0);
    } else if (b < PB_STU + PB_ITEM + PB_CONC) {
        proj_tile(conc_fusion, W_stu, EMB, N_CONC, (b - PB_STU - PB_ITEM) * 32,
                  p_cf, 2 * CNUM, 0);
    } else if (b < PB_TOT) {
        proj_tile(conc_fusion, W_item, EMB, N_CONC, (b - PB_STU - PB_ITEM - PB_CONC) * 32,
                  p_cf, 2 * CNUM, CNUM);
    } else if (threadIdx.x < 32) {
        // w-table block (independent of the projections).
        const int lane = threadIdx.x;
        const int sub  = lane & 15;
        const float sc = (lane >= 16) ? -0.5f : 0.5f;

        const float4 wA = __ldg(reinterpret_cast<const float4*>(w_pred) + sub * 2);
        const float4 wB = __ldg(reinterpret_cast<const float4*>(w_pred) + sub * 2 + 1);

        __half2 h0 = __floats2half2_rn(sc * wA.x, sc * wA.y);
        __half2 h1 = __floats2half2_rn(sc * wA.z, sc * wA.w);
        __half2 h2 = __floats2half2_rn(sc * wB.x, sc * wB.y);
        __half2 h3 = __floats2half2_rn(sc * wB.z, sc * wB.w);

        uint4 v;
        v.x = *reinterpret_cast<unsigned*>(&h0);
        v.y = *reinterpret_cast<unsigned*>(&h1);
        v.z = *reinterpret_cast<unsigned*>(&h2);
        v.w = *reinterpret_cast<unsigned*>(&h3);
        g_w_tbl[lane] = v;
    }
}

// One warp per edge (non-persistent — max TLP), SIDE-SPLIT: lanes 0-15
// student side, lanes 16-31 item side (-w folded into g_w_tbl). Lane owns
// 8 channels as one uint4 (4 half2). Fused conc row: one contiguous 512 B
// row per k. Tables hold 0.5*value: sig(x) = 0.5*(1 + tanh(x/2)).
// Joint 4-way reduction (7 shuffles); one outer sigmoid (tanh-form) per lane.
// Block output staged in smem -> single coalesced 32 B store.
__global__ __launch_bounds__(256)
void edge_kernel(const int*   __restrict__ stu_idx,
                 const int*   __restrict__ item_idx,
                 const int*   __restrict__ conc_idx,
                 const float* __restrict__ b_pred,
                 float*       __restrict__ out)
{
    __shared__ float sres[8];

    const int  lane = threadIdx.x & 31;
    const int  sub  = lane & 15;
    const bool hi   = lane >= 16;      // item side
    const int  e    = blockIdx.x * 8 + (threadIdx.x >> 5);

    // Side-selected index load: one LDG instead of two.
    const int* ibase = hi ? item_idx : stu_idx;
    const int  r     = __ldg(ibase + e);
    const int4 q4 = __ldg(reinterpret_cast<const int4*>(conc_idx) + e);
    const float b = __ldg(b_pred);

    const uint4 wraw = __ldg(g_w_tbl + lane);
    const __half2* wh = reinterpret_cast<const __half2*>(&wraw);

    // Own side's projection row chunk (8 channels = 16 bytes).
    const __half* pbase = hi ? g_item_proj : g_stu_proj;
    const uint4 praw = __ldg(reinterpret_cast<const uint4*>(pbase + r * CNUM) + sub);

    // Fused concept rows: warp reads contiguous 512 B (lane-indexed).
    const int qs[KC] = {q4.x, q4.y, q4.z, q4.w};
    uint4 craw[KC];
    #pragma unroll
    for (int k = 0; k < KC; k++)
        craw[k] = __ldg(reinterpret_cast<const uint4*>(g_conc_fused + qs[k] * (2 * CNUM)) + lane);

    const __half2* ph = reinterpret_cast<const __half2*>(&praw);

    float v[KC];
    #pragma unroll
    for (int k = 0; k < KC; k++) {
        const __half2* ch = reinterpret_cast<const __half2*>(&craw[k]);

        __half2 a2 = __hmul2(dg_tanh2(__hadd2(ph[0], ch[0])), wh[0]);
        a2 = __hfma2(dg_tanh2(__hadd2(ph[1], ch[1])), wh[1], a2);
        a2 = __hfma2(dg_tanh2(__hadd2(ph[2], ch[2])), wh[2], a2);
        a2 = __hfma2(dg_tanh2(__hadd2(ph[3], ch[3])), wh[3], a2);

        float2 f = __half22float2(a2);
        v[k] = f.x + f.y;
    }

    // Joint 4-way reduction: each 8-lane quarter ends up owning one k.
    const bool h16 = lane & 16;
    float a  = h16 ? v[1] : v[0];
    float as = h16 ? v[0] : v[1];
    a += __shfl_xor_sync(0xFFFFFFFFu, as, 16);
    float c  = h16 ? v[3] : v[2];
    float cs = h16 ? v[2] : v[3];
    c += __shfl_xor_sync(0xFFFFFFFFu, cs, 16);
    const bool h8 = lane & 8;
    float w  = h8 ? c : a;
    float ws = h8 ? a : c;
    w += __shfl_xor_sync(0xFFFFFFFFu, ws, 8);
    w += __shfl_xor_sync(0xFFFFFFFFu, w, 4);
    w += __shfl_xor_sync(0xFFFFFFFFu, w, 2);
    w += __shfl_xor_sync(0xFFFFFFFFu, w, 1);

    // One outer sigmoid per lane, then sum the 4 distinct quarters.
    float sig = dg_sigmoid(w + b);
    sig += __shfl_xor_sync(0xFFFFFFFFu, sig, 8);
    sig += __shfl_xor_sync(0xFFFFFFFFu, sig, 16);

    if (lane == 0) sres[threadIdx.x >> 5] = sig * 0.25f;
    __syncthreads();
    if (threadIdx.x < 8)
        out[blockIdx.x * 8 + threadIdx.x] = sres[threadIdx.x];
}

extern "C" void kernel_launch(void* const* d_in, const int* in_sizes, int n_in,
                              void* d_out, int out_size)
{
    const int*   stu_idx        = (const int*)  d_in[0];
    const int*   item_idx       = (const int*)  d_in[1];
    const int*   conc_idx       = (const int*)  d_in[2];
    const float* stu_fusion     = (const float*)d_in[3];
    const float* item_fusion    = (const float*)d_in[4];
    const float* concept_fusion = (const float*)d_in[5];
    const float* W_stu          = (const float*)d_in[6];
    const float* W_item         = (const float*)d_in[7];
    const float* w_pred         = (const float*)d_in[8];
    const float* b_pred         = (const float*)d_in[9];
    float*       out            = (float*)d_out;

    __half *p_sp, *p_ip, *p_cf;
    cudaGetSymbolAddress((void**)&p_sp, g_stu_proj);
    cudaGetSymbolAddress((void**)&p_ip, g_item_proj);
    cudaGetSymbolAddress((void**)&p_cf, g_conc_fused);

    proj_all<<<PB_TOT + 1, 256>>>(
        stu_fusion, item_fusion, concept_fusion, W_stu, W_item, w_pred,
        p_sp, p_ip, p_cf);

    edge_kernel<<<EDGES / 8, 256>>>(stu_idx, item_idx, conc_idx, b_pred, out);
}

// round 15
// speedup vs baseline: 1.0461x; 1.0461x over previous
#include <cuda_runtime.h>
#include <cuda_fp16.h>

#define N_STU   10000
#define N_ITEM  50000
#define N_CONC  2048
#define EDGES   250000
#define KC      4
#define EMB     64
#define CNUM    128

#define PB_STU   313     // ceil(10000/32)
#define PB_ITEM  1563    // ceil(50000/32)
#define PB_CONC  64      // 2048/32
#define PB_TOT   (PB_STU + PB_ITEM + 2 * PB_CONC)

// fp16 tables, values pre-multiplied by 0.5 (for the tanh half-angle form).
__device__ __half g_stu_proj [N_STU  * CNUM];      //  2.56 MB
__device__ __half g_item_proj[N_ITEM * CNUM];      // 12.8  MB
// Fused concept table: row q = [ stu side (128) | item side (128) ], 512 B/row.
__device__ __half g_conc_fused[N_CONC * 2 * CNUM]; //  1.0  MB
// Sign-folded, 0.5-scaled w as half2, one uint4 per lane (lanes 16-31 negated).
__device__ uint4  g_w_tbl[32];

namespace {

__device__ __forceinline__ __half2 dg_tanh2(__half2 x)
{
    unsigned r, xi = *reinterpret_cast<unsigned*>(&x);
    asm("tanh.approx.f16x2 %0, %1;" : "=r"(r) : "r"(xi));
    return *reinterpret_cast<__half2*>(&r);
}

__device__ __forceinline__ float dg_tanhf(float x)
{
    float r;
    asm("tanh.approx.f32 %0, %1;" : "=f"(r) : "f"(x));
    return r;
}

// sigmoid(x) = 0.5 + 0.5*tanh(x/2): ONE MUFU op, no divide.
__device__ __forceinline__ float dg_sigmoid(float x)
{
    return fmaf(0.5f, dg_tanhf(0.5f * x), 0.5f);
}

__device__ __forceinline__ void dg_mma(float d[4],
                                       unsigned a0, unsigned a1, unsigned a2, unsigned a3,
                                       unsigned b0, unsigned b1)
{
    asm volatile(
        "mma.sync.aligned.m16n8k8.row.col.f32.tf32.tf32.f32 "
        "{%0,%1,%2,%3}, {%4,%5,%6,%7}, {%8,%9}, {%0,%1,%2,%3};"
        : "+f"(d[0]), "+f"(d[1]), "+f"(d[2]), "+f"(d[3])
        : "r"(a0), "r"(a1), "r"(a2), "r"(a3), "r"(b0), "r"(b1));
}

// Tensor-core tile: out_half[row*stride + coloff + c] = 0.5 * sum_e fusion[row,e] * W[c, col_off+e]
// Block: 32 rows x 128 cols, 256 threads = 8 warps (2 m-tiles x 4 n-strips of 32).
// Raw f32 bits are fed to mma.tf32 (HW reads tf32 bits = implicit RZ truncate);
// no explicit cvt needed. Epilogue repacked through smem for STG.128.
__device__ __forceinline__
void proj_tile(const float* __restrict__ fusion,
               const float* __restrict__ W,
               int col_off, int nrows, int row0,
               __half* __restrict__ out, int out_stride, int out_coloff)
{
    // stride 68: 68 mod 32 == 4 -> fragment banks = 4*(lane/4) + lane%4, all distinct
    __shared__ unsigned Fsm[32][68];     // F[r][e], f32 bits (reused as store buffer)
    __shared__ unsigned Wsm[CNUM][68];   // W[c][e], f32 bits

    const int tid = threadIdx.x;

    // W: 128 rows x 16 float4
    for (int idx = tid; idx < CNUM * (EMB / 4); idx += 256) {
        int c = idx >> 4;
        int f = idx & 15;
        float4 v = __ldg(reinterpret_cast<const float4*>(W + c * (2 * EMB) + col_off) + f);
        Wsm[c][f * 4 + 0] = __float_as_uint(v.x);
        Wsm[c][f * 4 + 1] = __float_as_uint(v.y);
        Wsm[c][f * 4 + 2] = __float_as_uint(v.z);
        Wsm[c][f * 4 + 3] = __float_as_uint(v.w);
    }
    // F: 32 rows x 16 float4
    for (int idx = tid; idx < 32 * (EMB / 4); idx += 256) {
        int r = idx >> 4;
        int f = idx & 15;
        int row = row0 + r;
        float4 v = make_float4(0.f, 0.f, 0.f, 0.f);
        if (row < nrows)
            v = __ldg(reinterpret_cast<const float4*>(fusion + row * EMB) + f);
        Fsm[r][f * 4 + 0] = __float_as_uint(v.x);
        Fsm[r][f * 4 + 1] = __float_as_uint(v.y);
        Fsm[r][f * 4 + 2] = __float_as_uint(v.z);
        Fsm[r][f * 4 + 3] = __float_as_uint(v.w);
    }
    __syncthreads();

    const int warp = tid >> 5;
    const int lane = tid & 31;
    const int qr   = lane >> 2;   // 0..7
    const int qc   = lane & 3;    // 0..3

    const int r0 = (warp & 1) * 16;        // m-tile
    const int n0 = (warp >> 1) * 32;       // n-strip

    float d[4][4];
    #pragma unroll
    for (int nt = 0; nt < 4; nt++)
        #pragma unroll
        for (int j = 0; j < 4; j++) d[nt][j] = 0.0f;

    #pragma unroll
    for (int ks = 0; ks < 8; ks++) {
        const int k0 = ks * 8;
        unsigned a0 = Fsm[r0 + qr    ][k0 + qc    ];
        unsigned a1 = Fsm[r0 + qr + 8][k0 + qc    ];
        unsigned a2 = Fsm[r0 + qr    ][k0 + qc + 4];
        unsigned a3 = Fsm[r0 + qr + 8][k0 + qc + 4];
        #pragma unroll
        for (int nt = 0; nt < 4; nt++) {
            const int n = n0 + nt * 8;
            unsigned b0 = Wsm[n + qr][k0 + qc    ];
            unsigned b1 = Wsm[n + qr][k0 + qc + 4];
            dg_mma(d[nt], a0, a1, a2, a3, b0, b1);
        }
    }

    // Repack through smem for coalesced STG.128.
    // Buffer: 32 rows x 128 halfs, row stride 136 halfs (272 B = 68 words).
    // STS bank = (68*r + col/2) % 32 = (4*qr + qc): conflict-free.
    // Total 32*136*2 = 8704 B = sizeof(Fsm): exact reuse.
    __syncthreads();   // done reading Fsm
    __half* sbuf = reinterpret_cast<__half*>(&Fsm[0][0]);
    #pragma unroll
    for (int nt = 0; nt < 4; nt++) {
        const int col = n0 + nt * 8 + qc * 2;
        *reinterpret_cast<__half2*>(sbuf + (r0 + qr) * 136 + col) =
            __floats2half2_rn(d[nt][0] * 0.5f, d[nt][1] * 0.5f);
        *reinterpret_cast<__half2*>(sbuf + (r0 + qr + 8) * 136 + col) =
            __floats2half2_rn(d[nt][2] * 0.5f, d[nt][3] * 0.5f);
    }
    __syncthreads();

    // 32 rows x 16 uint4 = 512 stores; thread t -> row t>>3, chunks (t&7), (t&7)+8.
    {
        const int r = tid >> 3;
        const int j = tid & 7;
        const int row = row0 + r;
        if (row < nrows) {
            const uint4* src = reinterpret_cast<const uint4*>(sbuf + r * 136);
            uint4* dst = reinterpret_cast<uint4*>(out + row * out_stride + out_coloff);
            dst[j]     = src[j];
            dst[j + 8] = src[j + 8];
        }
    }
}

} // anonymous namespace

// All four projections + the w-table build in ONE launch.
// Block PB_TOT (the extra last block) builds the sign-folded w table.
__global__ __launch_bounds__(256)
void proj_all(const float* __restrict__ stu_fusion,
              const float* __restrict__ item_fusion,
              const float* __restrict__ conc_fusion,
              const float* __restrict__ W_stu,
              const float* __restrict__ W_item,
              const float* __restrict__ w_pred,
              __half* p_sp, __half* p_ip, __half* p_cf)
{
    int b = blockIdx.x;
    if (b < PB_STU) {
        proj_tile(stu_fusion, W_stu, 0, N_STU, b * 32, p_sp, CNUM, 0);
    } else if (b < PB_STU + PB_ITEM) {
        proj_tile(item_fusion, W_item, 0, N_ITEM, (b - PB_STU) * 32, p_ip, CNUM, 0);
    } else if (b < PB_STU + PB_ITEM + PB_CONC) {
        proj_tile(conc_fusion, W_stu, EMB, N_CONC, (b - PB_STU - PB_ITEM) * 32,
                  p_cf, 2 * CNUM, 0);
    } else if (b < PB_TOT) {
        proj_tile(conc_fusion, W_item, EMB, N_CONC, (b - PB_STU - PB_ITEM - PB_CONC) * 32,
                  p_cf, 2 * CNUM, CNUM);
    } else if (threadIdx.x < 32) {
        // w-table block (independent of the projections).
        const int lane = threadIdx.x;
        const int sub  = lane & 15;
        const float sc = (lane >= 16) ? -0.5f : 0.5f;

        const float4 wA = __ldg(reinterpret_cast<const float4*>(w_pred) + sub * 2);
        const float4 wB = __ldg(reinterpret_cast<const float4*>(w_pred) + sub * 2 + 1);

        __half2 h0 = __floats2half2_rn(sc * wA.x, sc * wA.y);
        __half2 h1 = __floats2half2_rn(sc * wA.z, sc * wA.w);
        __half2 h2 = __floats2half2_rn(sc * wB.x, sc * wB.y);
        __half2 h3 = __floats2half2_rn(sc * wB.z, sc * wB.w);

        uint4 v;
        v.x = *reinterpret_cast<unsigned*>(&h0);
        v.y = *reinterpret_cast<unsigned*>(&h1);
        v.z = *reinterpret_cast<unsigned*>(&h2);
        v.w = *reinterpret_cast<unsigned*>(&h3);
        g_w_tbl[lane] = v;
    }
}

// One warp per edge (non-persistent — max TLP), SIDE-SPLIT: lanes 0-15
// student side, lanes 16-31 item side (-w folded into g_w_tbl). Lane owns
// 8 channels as one uint4 (4 half2). Fused conc row: one contiguous 512 B
// row per k. Tables hold 0.5*value: sig(x) = 0.5*(1 + tanh(x/2)).
// Joint 4-way reduction (7 shuffles); one outer sigmoid (tanh-form) per lane.
// Output: direct lane-0 STG.32 (fire-and-forget; NO block barrier).
__global__ __launch_bounds__(256)
void edge_kernel(const int*   __restrict__ stu_idx,
                 const int*   __restrict__ item_idx,
                 const int*   __restrict__ conc_idx,
                 const float* __restrict__ b_pred,
                 float*       __restrict__ out)
{
    const int  lane = threadIdx.x & 31;
    const int  sub  = lane & 15;
    const bool hi   = lane >= 16;      // item side
    const int  e    = blockIdx.x * 8 + (threadIdx.x >> 5);

    // Side-selected index load: one broadcast LDG instead of two.
    const int* ibase = hi ? item_idx : stu_idx;
    const int  r     = __ldg(ibase + e);
    const int4 q4 = __ldg(reinterpret_cast<const int4*>(conc_idx) + e);
    const float b = __ldg(b_pred);

    const uint4 wraw = __ldg(g_w_tbl + lane);
    const __half2* wh = reinterpret_cast<const __half2*>(&wraw);

    // Own side's projection row chunk (8 channels = 16 bytes).
    const __half* pbase = hi ? g_item_proj : g_stu_proj;
    const uint4 praw = __ldg(reinterpret_cast<const uint4*>(pbase + r * CNUM) + sub);

    // Fused concept rows: warp reads contiguous 512 B (lane-indexed).
    const int qs[KC] = {q4.x, q4.y, q4.z, q4.w};
    uint4 craw[KC];
    #pragma unroll
    for (int k = 0; k < KC; k++)
        craw[k] = __ldg(reinterpret_cast<const uint4*>(g_conc_fused + qs[k] * (2 * CNUM)) + lane);

    const __half2* ph = reinterpret_cast<const __half2*>(&praw);

    float v[KC];
    #pragma unroll
    for (int k = 0; k < KC; k++) {
        const __half2* ch = reinterpret_cast<const __half2*>(&craw[k]);

        __half2 a2 = __hmul2(dg_tanh2(__hadd2(ph[0], ch[0])), wh[0]);
        a2 = __hfma2(dg_tanh2(__hadd2(ph[1], ch[1])), wh[1], a2);
        a2 = __hfma2(dg_tanh2(__hadd2(ph[2], ch[2])), wh[2], a2);
        a2 = __hfma2(dg_tanh2(__hadd2(ph[3], ch[3])), wh[3], a2);

        float2 f = __half22float2(a2);
        v[k] = f.x + f.y;
    }

    // Joint 4-way reduction: each 8-lane quarter ends up owning one k.
    const bool h16 = lane & 16;
    float a  = h16 ? v[1] : v[0];
    float as = h16 ? v[0] : v[1];
    a += __shfl_xor_sync(0xFFFFFFFFu, as, 16);
    float c  = h16 ? v[3] : v[2];
    float cs = h16 ? v[2] : v[3];
    c += __shfl_xor_sync(0xFFFFFFFFu, cs, 16);
    const bool h8 = lane & 8;
    float w  = h8 ? c : a;
    float ws = h8 ? a : c;
    w += __shfl_xor_sync(0xFFFFFFFFu, ws, 8);
    w += __shfl_xor_sync(0xFFFFFFFFu, w, 4);
    w += __shfl_xor_sync(0xFFFFFFFFu, w, 2);
    w += __shfl_xor_sync(0xFFFFFFFFu, w, 1);

    // One outer sigmoid per lane, then sum the 4 distinct quarters.
    float sig = dg_sigmoid(w + b);
    sig += __shfl_xor_sync(0xFFFFFFFFu, sig, 8);
    sig += __shfl_xor_sync(0xFFFFFFFFu, sig, 16);

    if (lane == 0) out[e] = sig * 0.25f;
}

extern "C" void kernel_launch(void* const* d_in, const int* in_sizes, int n_in,
                              void* d_out, int out_size)
{
    const int*   stu_idx        = (const int*)  d_in[0];
    const int*   item_idx       = (const int*)  d_in[1];
    const int*   conc_idx       = (const int*)  d_in[2];
    const float* stu_fusion     = (const float*)d_in[3];
    const float* item_fusion    = (const float*)d_in[4];
    const float* concept_fusion = (const float*)d_in[5];
    const float* W_stu          = (const float*)d_in[6];
    const float* W_item         = (const float*)d_in[7];
    const float* w_pred         = (const float*)d_in[8];
    const float* b_pred         = (const float*)d_in[9];
    float*       out            = (float*)d_out;

    __half *p_sp, *p_ip, *p_cf;
    cudaGetSymbolAddress((void**)&p_sp, g_stu_proj);
    cudaGetSymbolAddress((void**)&p_ip, g_item_proj);
    cudaGetSymbolAddress((void**)&p_cf, g_conc_fused);

    proj_all<<<PB_TOT + 1, 256>>>(
        stu_fusion, item_fusion, concept_fusion, W_stu, W_item, w_pred,
        p_sp, p_ip, p_cf);

    edge_kernel<<<EDGES / 8, 256>>>(stu_idx, item_idx, conc_idx, b_pred, out);
}

// round 16
// speedup vs baseline: 1.0470x; 1.0008x over previous
#include <cuda_runtime.h>
#include <cuda_fp16.h>

#define N_STU   10000
#define N_ITEM  50000
#define N_CONC  2048
#define EDGES   250000
#define KC      4
#define EMB     64
#define CNUM    128

#define PB_STU   313     // ceil(10000/32)
#define PB_ITEM  1563    // ceil(50000/32)
#define PB_CONC  64      // 2048/32
#define PB_TOT   (PB_STU + PB_ITEM + 2 * PB_CONC)

// fp16 tables, values pre-multiplied by 0.5 (for the tanh half-angle form).
__device__ __half g_stu_proj [N_STU  * CNUM];      //  2.56 MB
__device__ __half g_item_proj[N_ITEM * CNUM];      // 12.8  MB
// Fused concept table: row q = [ stu side (128) | item side (128) ], 512 B/row.
__device__ __half g_conc_fused[N_CONC * 2 * CNUM]; //  1.0  MB
// Sign-folded, 0.5-scaled w as half2, one uint4 per lane (lanes 16-31 negated).
__device__ uint4  g_w_tbl[32];

namespace {

__device__ __forceinline__ __half2 dg_tanh2(__half2 x)
{
    unsigned r, xi = *reinterpret_cast<unsigned*>(&x);
    asm("tanh.approx.f16x2 %0, %1;" : "=r"(r) : "r"(xi));
    return *reinterpret_cast<__half2*>(&r);
}

__device__ __forceinline__ float dg_tanhf(float x)
{
    float r;
    asm("tanh.approx.f32 %0, %1;" : "=f"(r) : "f"(x));
    return r;
}

// sigmoid(x) = 0.5 + 0.5*tanh(x/2): ONE MUFU op, no divide.
__device__ __forceinline__ float dg_sigmoid(float x)
{
    return fmaf(0.5f, dg_tanhf(0.5f * x), 0.5f);
}

__device__ __forceinline__ void dg_mma(float d[4],
                                       unsigned a0, unsigned a1, unsigned a2, unsigned a3,
                                       unsigned b0, unsigned b1)
{
    asm volatile(
        "mma.sync.aligned.m16n8k8.row.col.f32.tf32.tf32.f32 "
        "{%0,%1,%2,%3}, {%4,%5,%6,%7}, {%8,%9}, {%0,%1,%2,%3};"
        : "+f"(d[0]), "+f"(d[1]), "+f"(d[2]), "+f"(d[3])
        : "r"(a0), "r"(a1), "r"(a2), "r"(a3), "r"(b0), "r"(b1));
}

// Tensor-core tile: out_half[row*stride + coloff + c] = 0.5 * sum_e fusion[row,e] * W[c, col_off+e]
// Block: 32 rows x 128 cols, 256 threads = 8 warps (2 m-tiles x 4 n-strips of 32).
// Raw f32 bits are fed to mma.tf32 (HW reads tf32 bits = implicit RZ truncate).
__device__ __forceinline__
void proj_tile(const float* __restrict__ fusion,
               const float* __restrict__ W,
               int col_off, int nrows, int row0,
               __half* __restrict__ out, int out_stride, int out_coloff)
{
    // stride 68: 68 mod 32 == 4 -> fragment banks = 4*(lane/4) + lane%4, all distinct
    __shared__ unsigned Fsm[32][68];     // F[r][e], f32 bits (reused as store buffer)
    __shared__ unsigned Wsm[CNUM][68];   // W[c][e], f32 bits

    const int tid = threadIdx.x;

    // W: 128 rows x 16 float4
    for (int idx = tid; idx < CNUM * (EMB / 4); idx += 256) {
        int c = idx >> 4;
        int f = idx & 15;
        float4 v = __ldg(reinterpret_cast<const float4*>(W + c * (2 * EMB) + col_off) + f);
        Wsm[c][f * 4 + 0] = __float_as_uint(v.x);
        Wsm[c][f * 4 + 1] = __float_as_uint(v.y);
        Wsm[c][f * 4 + 2] = __float_as_uint(v.z);
        Wsm[c][f * 4 + 3] = __float_as_uint(v.w);
    }
    // F: 32 rows x 16 float4
    for (int idx = tid; idx < 32 * (EMB / 4); idx += 256) {
        int r = idx >> 4;
        int f = idx & 15;
        int row = row0 + r;
        float4 v = make_float4(0.f, 0.f, 0.f, 0.f);
        if (row < nrows)
            v = __ldg(reinterpret_cast<const float4*>(fusion + row * EMB) + f);
        Fsm[r][f * 4 + 0] = __float_as_uint(v.x);
        Fsm[r][f * 4 + 1] = __float_as_uint(v.y);
        Fsm[r][f * 4 + 2] = __float_as_uint(v.z);
        Fsm[r][f * 4 + 3] = __float_as_uint(v.w);
    }
    __syncthreads();

    const int warp = tid >> 5;
    const int lane = tid & 31;
    const int qr   = lane >> 2;   // 0..7
    const int qc   = lane & 3;    // 0..3

    const int r0 = (warp & 1) * 16;        // m-tile
    const int n0 = (warp >> 1) * 32;       // n-strip

    float d[4][4];
    #pragma unroll
    for (int nt = 0; nt < 4; nt++)
        #pragma unroll
        for (int j = 0; j < 4; j++) d[nt][j] = 0.0f;

    #pragma unroll
    for (int ks = 0; ks < 8; ks++) {
        const int k0 = ks * 8;
        unsigned a0 = Fsm[r0 + qr    ][k0 + qc    ];
        unsigned a1 = Fsm[r0 + qr + 8][k0 + qc    ];
        unsigned a2 = Fsm[r0 + qr    ][k0 + qc + 4];
        unsigned a3 = Fsm[r0 + qr + 8][k0 + qc + 4];
        #pragma unroll
        for (int nt = 0; nt < 4; nt++) {
            const int n = n0 + nt * 8;
            unsigned b0 = Wsm[n + qr][k0 + qc    ];
            unsigned b1 = Wsm[n + qr][k0 + qc + 4];
            dg_mma(d[nt], a0, a1, a2, a3, b0, b1);
        }
    }

    // Repack through smem for coalesced STG.128.
    // Buffer: 32 rows x 128 halfs, row stride 136 halfs (272 B = 68 words).
    // STS bank = (68*r + col/2) % 32 = (4*qr + qc): conflict-free.
    __syncthreads();   // done reading Fsm
    __half* sbuf = reinterpret_cast<__half*>(&Fsm[0][0]);
    #pragma unroll
    for (int nt = 0; nt < 4; nt++) {
        const int col = n0 + nt * 8 + qc * 2;
        *reinterpret_cast<__half2*>(sbuf + (r0 + qr) * 136 + col) =
            __floats2half2_rn(d[nt][0] * 0.5f, d[nt][1] * 0.5f);
        *reinterpret_cast<__half2*>(sbuf + (r0 + qr + 8) * 136 + col) =
            __floats2half2_rn(d[nt][2] * 0.5f, d[nt][3] * 0.5f);
    }
    __syncthreads();

    // 32 rows x 16 uint4 = 512 stores; thread t -> row t>>3, chunks (t&7), (t&7)+8.
    {
        const int r = tid >> 3;
        const int j = tid & 7;
        const int row = row0 + r;
        if (row < nrows) {
            const uint4* src = reinterpret_cast<const uint4*>(sbuf + r * 136);
            uint4* dst = reinterpret_cast<uint4*>(out + row * out_stride + out_coloff);
            dst[j]     = src[j];
            dst[j + 8] = src[j + 8];
        }
    }
}

} // anonymous namespace

// All four projections + the w-table build in ONE launch.
// Block PB_TOT (the extra last block) builds the sign-folded w table.
// Each block signals PDL dependents after its stores.
__global__ __launch_bounds__(256)
void proj_all(const float* __restrict__ stu_fusion,
              const float* __restrict__ item_fusion,
              const float* __restrict__ conc_fusion,
              const float* __restrict__ W_stu,
              const float* __restrict__ W_item,
              const float* __restrict__ w_pred,
              __half* p_sp, __half* p_ip, __half* p_cf)
{
    int b = blockIdx.x;
    if (b < PB_STU) {
        proj_tile(stu_fusion, W_stu, 0, N_STU, b * 32, p_sp, CNUM, 0);
    } else if (b < PB_STU + PB_ITEM) {
        proj_tile(item_fusion, W_item, 0, N_ITEM, (b - PB_STU) * 32, p_ip, CNUM, 0);
    } else if (b < PB_STU + PB_ITEM + PB_CONC) {
        proj_tile(conc_fusion, W_stu, EMB, N_CONC, (b - PB_STU - PB_ITEM) * 32,
                  p_cf, 2 * CNUM, 0);
    } else if (b < PB_TOT) {
        proj_tile(conc_fusion, W_item, EMB, N_CONC, (b - PB_STU - PB_ITEM - PB_CONC) * 32,
                  p_cf, 2 * CNUM, CNUM);
    } else if (threadIdx.x < 32) {
        // w-table block (independent of the projections).
        const int lane = threadIdx.x;
        const int sub  = lane & 15;
        const float sc = (lane >= 16) ? -0.5f : 0.5f;

        const float4 wA = __ldg(reinterpret_cast<const float4*>(w_pred) + sub * 2);
        const float4 wB = __ldg(reinterpret_cast<const float4*>(w_pred) + sub * 2 + 1);

        __half2 h0 = __floats2half2_rn(sc * wA.x, sc * wA.y);
        __half2 h1 = __floats2half2_rn(sc * wA.z, sc * wA.w);
        __half2 h2 = __floats2half2_rn(sc * wB.x, sc * wB.y);
        __half2 h3 = __floats2half2_rn(sc * wB.z, sc * wB.w);

        uint4 v;
        v.x = *reinterpret_cast<unsigned*>(&h0);
        v.y = *reinterpret_cast<unsigned*>(&h1);
        v.z = *reinterpret_cast<unsigned*>(&h2);
        v.w = *reinterpret_cast<unsigned*>(&h3);
        g_w_tbl[lane] = v;
    }

    // PDL: allow the edge kernel's blocks to launch; its griddepcontrol.wait
    // orders against all stores program-ordered before this point.
    asm volatile("griddepcontrol.launch_dependents;" ::: "memory");
}

// One warp per edge (non-persistent — max TLP), SIDE-SPLIT: lanes 0-15
// student side, lanes 16-31 item side (-w folded into g_w_tbl). Lane owns
// 8 channels as one uint4 (4 half2). Fused conc row: one contiguous 512 B
// row per k. Tables hold 0.5*value: sig(x) = 0.5*(1 + tanh(x/2)).
// PDL: the preamble (index/bias loads, independent of proj output) runs
// before griddepcontrol.wait; table reads come after.
__global__ __launch_bounds__(256)
void edge_kernel(const int*   __restrict__ stu_idx,
                 const int*   __restrict__ item_idx,
                 const int*   __restrict__ conc_idx,
                 const float* __restrict__ b_pred,
                 float*       __restrict__ out)
{
    const int  lane = threadIdx.x & 31;
    const int  sub  = lane & 15;
    const bool hi   = lane >= 16;      // item side
    const int  e    = blockIdx.x * 8 + (threadIdx.x >> 5);

    // ---- Independent of proj output: issue before the PDL wait. ----
    const int* ibase = hi ? item_idx : stu_idx;
    const int  r     = __ldg(ibase + e);
    const int4 q4 = __ldg(reinterpret_cast<const int4*>(conc_idx) + e);
    const float b = __ldg(b_pred);
    const int qs[KC] = {q4.x, q4.y, q4.z, q4.w};

    // ---- Wait for proj_all's stores to be visible. ----
    asm volatile("griddepcontrol.wait;" ::: "memory");

    const uint4 wraw = __ldg(g_w_tbl + lane);
    const __half2* wh = reinterpret_cast<const __half2*>(&wraw);

    // Own side's projection row chunk (8 channels = 16 bytes).
    const __half* pbase = hi ? g_item_proj : g_stu_proj;
    const uint4 praw = __ldg(reinterpret_cast<const uint4*>(pbase + r * CNUM) + sub);

    // Fused concept rows: warp reads contiguous 512 B (lane-indexed).
    uint4 craw[KC];
    #pragma unroll
    for (int k = 0; k < KC; k++)
        craw[k] = __ldg(reinterpret_cast<const uint4*>(g_conc_fused + qs[k] * (2 * CNUM)) + lane);

    const __half2* ph = reinterpret_cast<const __half2*>(&praw);

    float v[KC];
    #pragma unroll
    for (int k = 0; k < KC; k++) {
        const __half2* ch = reinterpret_cast<const __half2*>(&craw[k]);

        __half2 a2 = __hmul2(dg_tanh2(__hadd2(ph[0], ch[0])), wh[0]);
        a2 = __hfma2(dg_tanh2(__hadd2(ph[1], ch[1])), wh[1], a2);
        a2 = __hfma2(dg_tanh2(__hadd2(ph[2], ch[2])), wh[2], a2);
        a2 = __hfma2(dg_tanh2(__hadd2(ph[3], ch[3])), wh[3], a2);

        float2 f = __half22float2(a2);
        v[k] = f.x + f.y;
    }

    // Joint 4-way reduction: each 8-lane quarter ends up owning one k.
    const bool h16 = lane & 16;
    float a  = h16 ? v[1] : v[0];
    float as = h16 ? v[0] : v[1];
    a += __shfl_xor_sync(0xFFFFFFFFu, as, 16);
    float c  = h16 ? v[3] : v[2];
    float cs = h16 ? v[2] : v[3];
    c += __shfl_xor_sync(0xFFFFFFFFu, cs, 16);
    const bool h8 = lane & 8;
    float w  = h8 ? c : a;
    float ws = h8 ? a : c;
    w += __shfl_xor_sync(0xFFFFFFFFu, ws, 8);
    w += __shfl_xor_sync(0xFFFFFFFFu, w, 4);
    w += __shfl_xor_sync(0xFFFFFFFFu, w, 2);
    w += __shfl_xor_sync(0xFFFFFFFFu, w, 1);

    // One outer sigmoid per lane, then sum the 4 distinct quarters.
    float sig = dg_sigmoid(w + b);
    sig += __shfl_xor_sync(0xFFFFFFFFu, sig, 8);
    sig += __shfl_xor_sync(0xFFFFFFFFu, sig, 16);

    if (lane == 0) out[e] = sig * 0.25f;
}

extern "C" void kernel_launch(void* const* d_in, const int* in_sizes, int n_in,
                              void* d_out, int out_size)
{
    const int*   stu_idx        = (const int*)  d_in[0];
    const int*   item_idx       = (const int*)  d_in[1];
    const int*   conc_idx       = (const int*)  d_in[2];
    const float* stu_fusion     = (const float*)d_in[3];
    const float* item_fusion    = (const float*)d_in[4];
    const float* concept_fusion = (const float*)d_in[5];
    const float* W_stu          = (const float*)d_in[6];
    const float* W_item         = (const float*)d_in[7];
    const float* w_pred         = (const float*)d_in[8];
    const float* b_pred         = (const float*)d_in[9];
    float*       out            = (float*)d_out;

    __half *p_sp, *p_ip, *p_cf;
    cudaGetSymbolAddress((void**)&p_sp, g_stu_proj);
    cudaGetSymbolAddress((void**)&p_ip, g_item_proj);
    cudaGetSymbolAddress((void**)&p_cf, g_conc_fused);

    proj_all<<<PB_TOT + 1, 256>>>(
        stu_fusion, item_fusion, concept_fusion, W_stu, W_item, w_pred,
        p_sp, p_ip, p_cf);

    // Edge kernel with programmatic dependent launch: overlaps its preamble
    // with proj_all's tail; griddepcontrol.wait guards the table reads.
    cudaLaunchConfig_t cfg = {};
    cfg.gridDim  = dim3(EDGES / 8);
    cfg.blockDim = dim3(256);
    cudaLaunchAttribute attrs[1];
    attrs[0].id = cudaLaunchAttributeProgrammaticStreamSerialization;
    attrs[0].val.programmaticStreamSerializationAllowed = 1;
    cfg.attrs = attrs;
    cfg.numAttrs = 1;
    cudaLaunchKernelEx(&cfg, edge_kernel, stu_idx, item_idx, conc_idx, b_pred, out);
}

// round 17
// speedup vs baseline: 1.1010x; 1.0516x over previous
#include <cuda_runtime.h>
#include <cuda_fp16.h>

#define N_STU   10000
#define N_ITEM  50000
#define N_CONC  2048
#define EDGES   250000
#define KC      4
#define EMB     64
#define CNUM    128

// 64-row proj blocks
#define PB_STU   157     // ceil(10000/64)
#define PB_ITEM  782     // ceil(50000/64)
#define PB_CONC  32      // 2048/64
#define PB_TOT   (PB_STU + PB_ITEM + 2 * PB_CONC)   // 1003

// Dynamic smem: Wsm[128][68] + Fsm[2][32][68] (unsigned)
#define PROJ_SMEM_WORDS (CNUM * 68 + 2 * 32 * 68)
#define PROJ_SMEM_BYTES (PROJ_SMEM_WORDS * 4)       // 52224

// fp16 tables, values pre-multiplied by 0.5 (for the tanh half-angle form).
__device__ __half g_stu_proj [N_STU  * CNUM];      //  2.56 MB
__device__ __half g_item_proj[N_ITEM * CNUM];      // 12.8  MB
// Fused concept table: row q = [ stu side (128) | item side (128) ], 512 B/row.
__device__ __half g_conc_fused[N_CONC * 2 * CNUM]; //  1.0  MB
// Sign-folded, 0.5-scaled w as half2, one uint4 per lane (lanes 16-31 negated).
__device__ uint4  g_w_tbl[32];

namespace {

__device__ __forceinline__ __half2 dg_tanh2(__half2 x)
{
    unsigned r, xi = *reinterpret_cast<unsigned*>(&x);
    asm("tanh.approx.f16x2 %0, %1;" : "=r"(r) : "r"(xi));
    return *reinterpret_cast<__half2*>(&r);
}

__device__ __forceinline__ float dg_tanhf(float x)
{
    float r;
    asm("tanh.approx.f32 %0, %1;" : "=f"(r) : "f"(x));
    return r;
}

// sigmoid(x) = 0.5 + 0.5*tanh(x/2): ONE MUFU op, no divide.
__device__ __forceinline__ float dg_sigmoid(float x)
{
    return fmaf(0.5f, dg_tanhf(0.5f * x), 0.5f);
}

__device__ __forceinline__ void dg_mma(float d[4],
                                       unsigned a0, unsigned a1, unsigned a2, unsigned a3,
                                       unsigned b0, unsigned b1)
{
    asm volatile(
        "mma.sync.aligned.m16n8k8.row.col.f32.tf32.tf32.f32 "
        "{%0,%1,%2,%3}, {%4,%5,%6,%7}, {%8,%9}, {%0,%1,%2,%3};"
        : "+f"(d[0]), "+f"(d[1]), "+f"(d[2]), "+f"(d[3])
        : "r"(a0), "r"(a1), "r"(a2), "r"(a3), "r"(b0), "r"(b1));
}

// 64-row tensor-core tile. W staged ONCE per block; F double-buffered:
// tile 1's F loads are issued before tile 0's MMA loop and stored to smem
// after it (LDG latency hidden under compute). Raw f32 bits feed mma.tf32.
// Block: 256 threads = 8 warps (2 m-tiles x 4 n-strips of 32) per 32-row tile.
__device__ __forceinline__
void proj_tile64(const float* __restrict__ fusion,
                 const float* __restrict__ W,
                 int col_off, int nrows, int row0,
                 __half* __restrict__ out, int out_stride, int out_coloff,
                 unsigned* __restrict__ smem)
{
    // stride 68: 68 mod 32 == 4 -> fragment banks = 4*qr + qc, all distinct
    unsigned (*Wsm)[68]  = reinterpret_cast<unsigned(*)[68]>(smem);
    unsigned (*Fsm0)[68] = reinterpret_cast<unsigned(*)[68]>(smem + CNUM * 68);
    unsigned (*Fsm1)[68] = reinterpret_cast<unsigned(*)[68]>(smem + CNUM * 68 + 32 * 68);

    const int tid = threadIdx.x;

    // Stage W: 128 rows x 16 float4.
    for (int idx = tid; idx < CNUM * (EMB / 4); idx += 256) {
        int c = idx >> 4;
        int f = idx & 15;
        float4 v = __ldg(reinterpret_cast<const float4*>(W + c * (2 * EMB) + col_off) + f);
        Wsm[c][f * 4 + 0] = __float_as_uint(v.x);
        Wsm[c][f * 4 + 1] = __float_as_uint(v.y);
        Wsm[c][f * 4 + 2] = __float_as_uint(v.z);
        Wsm[c][f * 4 + 3] = __float_as_uint(v.w);
    }
    // Stage F tile 0: rows row0..row0+31, 32 x 16 float4.
    for (int idx = tid; idx < 32 * (EMB / 4); idx += 256) {
        int r = idx >> 4;
        int f = idx & 15;
        int row = row0 + r;
        float4 v = make_float4(0.f, 0.f, 0.f, 0.f);
        if (row < nrows)
            v = __ldg(reinterpret_cast<const float4*>(fusion + row * EMB) + f);
        Fsm0[r][f * 4 + 0] = __float_as_uint(v.x);
        Fsm0[r][f * 4 + 1] = __float_as_uint(v.y);
        Fsm0[r][f * 4 + 2] = __float_as_uint(v.z);
        Fsm0[r][f * 4 + 3] = __float_as_uint(v.w);
    }
    __syncthreads();

    const int warp = tid >> 5;
    const int lane = tid & 31;
    const int qr   = lane >> 2;   // 0..7
    const int qc   = lane & 3;    // 0..3
    const int r0   = (warp & 1) * 16;      // m-tile
    const int n0   = (warp >> 1) * 32;     // n-strip

    // Prefetch indices for F tile 1 (each thread: 2 float4).
    const int pr0 = tid >> 4,         pf0 = tid & 15;        // rows 0..15
    const int pr1 = (tid + 256) >> 4, pf1 = (tid + 256) & 15; // rows 16..31

    #pragma unroll
    for (int t = 0; t < 2; t++) {
        unsigned (*F)[68] = t ? Fsm1 : Fsm0;
        const int trow0 = row0 + t * 32;

        // Issue F1 global loads BEFORE tile-0 compute (latency hidden).
        float4 nf0, nf1;
        if (t == 0) {
            int g0 = row0 + 32 + pr0;
            int g1 = row0 + 32 + pr1;
            nf0 = make_float4(0.f, 0.f, 0.f, 0.f);
            nf1 = make_float4(0.f, 0.f, 0.f, 0.f);
            if (g0 < nrows) nf0 = __ldg(reinterpret_cast<const float4*>(fusion + g0 * EMB) + pf0);
            if (g1 < nrows) nf1 = __ldg(reinterpret_cast<const float4*>(fusion + g1 * EMB) + pf1);
        }

        float d[4][4];
        #pragma unroll
        for (int nt = 0; nt < 4; nt++)
            #pragma unroll
            for (int j = 0; j < 4; j++) d[nt][j] = 0.0f;

        #pragma unroll
        for (int ks = 0; ks < 8; ks++) {
            const int k0 = ks * 8;
            unsigned a0 = F[r0 + qr    ][k0 + qc    ];
            unsigned a1 = F[r0 + qr + 8][k0 + qc    ];
            unsigned a2 = F[r0 + qr    ][k0 + qc + 4];
            unsigned a3 = F[r0 + qr + 8][k0 + qc + 4];
            #pragma unroll
            for (int nt = 0; nt < 4; nt++) {
                const int n = n0 + nt * 8;
                unsigned b0 = Wsm[n + qr][k0 + qc    ];
                unsigned b1 = Wsm[n + qr][k0 + qc + 4];
                dg_mma(d[nt], a0, a1, a2, a3, b0, b1);
            }
        }

        // Store the prefetched F1 tile.
        if (t == 0) {
            Fsm1[pr0][pf0 * 4 + 0] = __float_as_uint(nf0.x);
            Fsm1[pr0][pf0 * 4 + 1] = __float_as_uint(nf0.y);
            Fsm1[pr0][pf0 * 4 + 2] = __float_as_uint(nf0.z);
            Fsm1[pr0][pf0 * 4 + 3] = __float_as_uint(nf0.w);
            Fsm1[pr1][pf1 * 4 + 0] = __float_as_uint(nf1.x);
            Fsm1[pr1][pf1 * 4 + 1] = __float_as_uint(nf1.y);
            Fsm1[pr1][pf1 * 4 + 2] = __float_as_uint(nf1.z);
            Fsm1[pr1][pf1 * 4 + 3] = __float_as_uint(nf1.w);
        }
        __syncthreads();   // F reads done (repack may clobber); Fsm1 visible

        // Repack tile t into its own (now free) F buffer for STG.128.
        // Row stride 136 halfs (272 B = 68 words): STS bank = 4*qr+qc, conflict-free.
        __half* sbuf = reinterpret_cast<__half*>(F);
        #pragma unroll
        for (int nt = 0; nt < 4; nt++) {
            const int col = n0 + nt * 8 + qc * 2;
            *reinterpret_cast<__half2*>(sbuf + (r0 + qr) * 136 + col) =
                __floats2half2_rn(d[nt][0] * 0.5f, d[nt][1] * 0.5f);
            *reinterpret_cast<__half2*>(sbuf + (r0 + qr + 8) * 136 + col) =
                __floats2half2_rn(d[nt][2] * 0.5f, d[nt][3] * 0.5f);
        }
        __syncthreads();

        // Coalesced stores: 32 rows x 16 uint4.
        {
            const int r = tid >> 3;
            const int j = tid & 7;
            const int row = trow0 + r;
            if (row < nrows) {
                const uint4* src = reinterpret_cast<const uint4*>(sbuf + r * 136);
                uint4* dst = reinterpret_cast<uint4*>(out + row * out_stride + out_coloff);
                dst[j]     = src[j];
                dst[j + 8] = src[j + 8];
            }
        }
        // No further sync needed: next iteration reads Fsm1/Wsm only (both settled).
    }
}

} // anonymous namespace

// All four projections + the w-table build in ONE launch.
// Block PB_TOT (the extra last block) builds the sign-folded w table.
// Each block signals PDL dependents after its stores.
__global__ __launch_bounds__(256)
void proj_all(const float* __restrict__ stu_fusion,
              const float* __restrict__ item_fusion,
              const float* __restrict__ conc_fusion,
              const float* __restrict__ W_stu,
              const float* __restrict__ W_item,
              const float* __restrict__ w_pred,
              __half* p_sp, __half* p_ip, __half* p_cf)
{
    extern __shared__ unsigned smem[];
    int b = blockIdx.x;
    if (b < PB_STU) {
        proj_tile64(stu_fusion, W_stu, 0, N_STU, b * 64, p_sp, CNUM, 0, smem);
    } else if (b < PB_STU + PB_ITEM) {
        proj_tile64(item_fusion, W_item, 0, N_ITEM, (b - PB_STU) * 64, p_ip, CNUM, 0, smem);
    } else if (b < PB_STU + PB_ITEM + PB_CONC) {
        proj_tile64(conc_fusion, W_stu, EMB, N_CONC, (b - PB_STU - PB_ITEM) * 64,
                    p_cf, 2 * CNUM, 0, smem);
    } else if (b < PB_TOT) {
        proj_tile64(conc_fusion, W_item, EMB, N_CONC, (b - PB_STU - PB_ITEM - PB_CONC) * 64,
                    p_cf, 2 * CNUM, CNUM, smem);
    } else if (threadIdx.x < 32) {
        // w-table block (independent of the projections).
        const int lane = threadIdx.x;
        const int sub  = lane & 15;
        const float sc = (lane >= 16) ? -0.5f : 0.5f;

        const float4 wA = __ldg(reinterpret_cast<const float4*>(w_pred) + sub * 2);
        const float4 wB = __ldg(reinterpret_cast<const float4*>(w_pred) + sub * 2 + 1);

        __half2 h0 = __floats2half2_rn(sc * wA.x, sc * wA.y);
        __half2 h1 = __floats2half2_rn(sc * wA.z, sc * wA.w);
        __half2 h2 = __floats2half2_rn(sc * wB.x, sc * wB.y);
        __half2 h3 = __floats2half2_rn(sc * wB.z, sc * wB.w);

        uint4 v;
        v.x = *reinterpret_cast<unsigned*>(&h0);
        v.y = *reinterpret_cast<unsigned*>(&h1);
        v.z = *reinterpret_cast<unsigned*>(&h2);
        v.w = *reinterpret_cast<unsigned*>(&h3);
        g_w_tbl[lane] = v;
    }

    // PDL: allow the edge kernel's blocks to launch.
    asm volatile("griddepcontrol.launch_dependents;" ::: "memory");
}

// One warp per edge (non-persistent — max TLP), SIDE-SPLIT: lanes 0-15
// student side, lanes 16-31 item side (-w folded into g_w_tbl). Lane owns
// 8 channels as one uint4 (4 half2). Fused conc row: one contiguous 512 B
// row per k. Tables hold 0.5*value: sig(x) = 0.5*(1 + tanh(x/2)).
// PDL: preamble loads run before griddepcontrol.wait; table reads after.
__global__ __launch_bounds__(256)
void edge_kernel(const int*   __restrict__ stu_idx,
                 const int*   __restrict__ item_idx,
                 const int*   __restrict__ conc_idx,
                 const float* __restrict__ b_pred,
                 float*       __restrict__ out)
{
    const int  lane = threadIdx.x & 31;
    const int  sub  = lane & 15;
    const bool hi   = lane >= 16;      // item side
    const int  e    = blockIdx.x * 8 + (threadIdx.x >> 5);

    // ---- Independent of proj output: issue before the PDL wait. ----
    const int* ibase = hi ? item_idx : stu_idx;
    const int  r     = __ldg(ibase + e);
    const int4 q4 = __ldg(reinterpret_cast<const int4*>(conc_idx) + e);
    const float b = __ldg(b_pred);
    const int qs[KC] = {q4.x, q4.y, q4.z, q4.w};

    // ---- Wait for proj_all's stores to be visible. ----
    asm volatile("griddepcontrol.wait;" ::: "memory");

    const uint4 wraw = __ldg(g_w_tbl + lane);
    const __half2* wh = reinterpret_cast<const __half2*>(&wraw);

    // Own side's projection row chunk (8 channels = 16 bytes).
    const __half* pbase = hi ? g_item_proj : g_stu_proj;
    const uint4 praw = __ldg(reinterpret_cast<const uint4*>(pbase + r * CNUM) + sub);

    // Fused concept rows: warp reads contiguous 512 B (lane-indexed).
    uint4 craw[KC];
    #pragma unroll
    for (int k = 0; k < KC; k++)
        craw[k] = __ldg(reinterpret_cast<const uint4*>(g_conc_fused + qs[k] * (2 * CNUM)) + lane);

    const __half2* ph = reinterpret_cast<const __half2*>(&praw);

    float v[KC];
    #pragma unroll
    for (int k = 0; k < KC; k++) {
        const __half2* ch = reinterpret_cast<const __half2*>(&craw[k]);

        __half2 a2 = __hmul2(dg_tanh2(__hadd2(ph[0], ch[0])), wh[0]);
        a2 = __hfma2(dg_tanh2(__hadd2(ph[1], ch[1])), wh[1], a2);
        a2 = __hfma2(dg_tanh2(__hadd2(ph[2], ch[2])), wh[2], a2);
        a2 = __hfma2(dg_tanh2(__hadd2(ph[3], ch[3])), wh[3], a2);

        float2 f = __half22float2(a2);
        v[k] = f.x + f.y;
    }

    // Joint 4-way reduction: each 8-lane quarter ends up owning one k.
    const bool h16 = lane & 16;
    float a  = h16 ? v[1] : v[0];
    float as = h16 ? v[0] : v[1];
    a += __shfl_xor_sync(0xFFFFFFFFu, as, 16);
    float c  = h16 ? v[3] : v[2];
    float cs = h16 ? v[2] : v[3];
    c += __shfl_xor_sync(0xFFFFFFFFu, cs, 16);
    const bool h8 = lane & 8;
    float w  = h8 ? c : a;
    float ws = h8 ? a : c;
    w += __shfl_xor_sync(0xFFFFFFFFu, ws, 8);
    w += __shfl_xor_sync(0xFFFFFFFFu, w, 4);
    w += __shfl_xor_sync(0xFFFFFFFFu, w, 2);
    w += __shfl_xor_sync(0xFFFFFFFFu, w, 1);

    // One outer sigmoid per lane, then sum the 4 distinct quarters.
    float sig = dg_sigmoid(w + b);
    sig += __shfl_xor_sync(0xFFFFFFFFu, sig, 8);
    sig += __shfl_xor_sync(0xFFFFFFFFu, sig, 16);

    if (lane == 0) out[e] = sig * 0.25f;
}

extern "C" void kernel_launch(void* const* d_in, const int* in_sizes, int n_in,
                              void* d_out, int out_size)
{
    const int*   stu_idx        = (const int*)  d_in[0];
    const int*   item_idx       = (const int*)  d_in[1];
    const int*   conc_idx       = (const int*)  d_in[2];
    const float* stu_fusion     = (const float*)d_in[3];
    const float* item_fusion    = (const float*)d_in[4];
    const float* concept_fusion = (const float*)d_in[5];
    const float* W_stu          = (const float*)d_in[6];
    const float* W_item         = (const float*)d_in[7];
    const float* w_pred         = (const float*)d_in[8];
    const float* b_pred         = (const float*)d_in[9];
    float*       out            = (float*)d_out;

    __half *p_sp, *p_ip, *p_cf;
    cudaGetSymbolAddress((void**)&p_sp, g_stu_proj);
    cudaGetSymbolAddress((void**)&p_ip, g_item_proj);
    cudaGetSymbolAddress((void**)&p_cf, g_conc_fused);

    cudaFuncSetAttribute(proj_all, cudaFuncAttributeMaxDynamicSharedMemorySize,
                         PROJ_SMEM_BYTES);

    proj_all<<<PB_TOT + 1, 256, PROJ_SMEM_BYTES>>>(
        stu_fusion, item_fusion, concept_fusion, W_stu, W_item, w_pred,
        p_sp, p_ip, p_cf);

    // Edge kernel with programmatic dependent launch.
    cudaLaunchConfig_t cfg = {};
    cfg.gridDim  = dim3(EDGES / 8);
    cfg.blockDim = dim3(256);
    cudaLaunchAttribute attrs[1];
    attrs[0].id = cudaLaunchAttributeProgrammaticStreamSerialization;
    attrs[0].val.programmaticStreamSerializationAllowed = 1;
    cfg.attrs = attrs;
    cfg.numAttrs = 1;
    cudaLaunchKernelEx(&cfg, edge_kernel, stu_idx, item_idx, conc_idx, b_pred, out);
}